// round 14
// baseline (speedup 1.0000x reference)
#include <cuda_runtime.h>
#include <cuda_fp16.h>
#include <math.h>
#include <stdint.h>

#define LSEQ 2048
#define DM 768
#define DI 1536
#define DS 16
#define DTR 48
#define DCONV 4
#define OUTD 128
#define PROJW (DTR + 2*DS)   // 80
#define NLAYER 2
#define ISPLIT 2
#define XSPLIT 16
#define OSPLIT 3
#define HSPLIT 12
#define NCHUNK 32
#define CLEN (LSEQ / NCHUNK)   // 64
#define DN (DI * DS)           // 24576

// ---------------- scratch ----------------
__device__ float g_x[LSEQ*DM];
__device__ float g_ipp[ISPLIT*LSEQ*2*DI];
__device__ float g_xc[LSEQ*DI];
__device__ float g_res[LSEQ*DI];
__device__ float g_proj[LSEQ*PROJW];
__device__ float g_projp[XSPLIT*LSEQ*PROJW];
__device__ float g_delta[LSEQ*DI];
__device__ float g_yp[OSPLIT*LSEQ*DM];
__device__ float g_headp[HSPLIT*LSEQ*OUTD];
__device__ float g_carryA[NCHUNK*DN];
__device__ float g_carryB[NCHUNK*DN];
// fp16 weights + activations
__device__ __half g_ipw16[NLAYER*2*DI*DM];
__device__ __half g_xpw16[NLAYER*PROJW*DI];
__device__ __half g_dtw16[NLAYER*DI*DTR];
__device__ __half g_opw16[NLAYER*DM*DI];
__device__ __half g_hw16[OUTD*DM];
__device__ __half g_xn16[LSEQ*DM];
__device__ __half g_xch[LSEQ*DI];
__device__ __half g_projh[LSEQ*PROJW];
__device__ __half g_yh[LSEQ*DI];

__device__ __forceinline__ uint32_t smem_u32(const void* p) {
    uint32_t a;
    asm("{ .reg .u64 t; cvta.to.shared.u64 t, %1; cvt.u32.u64 %0, t; }" : "=r"(a) : "l"(p));
    return a;
}
__device__ __forceinline__ void ldsm_x4(uint32_t& r0, uint32_t& r1, uint32_t& r2, uint32_t& r3, uint32_t addr) {
    asm volatile("ldmatrix.sync.aligned.m8n8.x4.shared.b16 {%0,%1,%2,%3}, [%4];"
                 : "=r"(r0), "=r"(r1), "=r"(r2), "=r"(r3) : "r"(addr));
}
__device__ __forceinline__ void mma16816(float* c, const uint32_t* a, uint32_t b0, uint32_t b1) {
    asm volatile("mma.sync.aligned.m16n8k16.row.col.f32.f16.f16.f32 "
                 "{%0,%1,%2,%3}, {%4,%5,%6,%7}, {%8,%9}, {%0,%1,%2,%3};"
                 : "+f"(c[0]), "+f"(c[1]), "+f"(c[2]), "+f"(c[3])
                 : "r"(a[0]), "r"(a[1]), "r"(a[2]), "r"(a[3]), "r"(b0), "r"(b1));
}
__device__ __forceinline__ void cpasync16(uint32_t dst, const void* src, int sz) {
    asm volatile("cp.async.cg.shared.global [%0], [%1], 16, %2;"
                 :: "r"(dst), "l"(src), "r"(sz) : "memory");
}

// ---------------- fp16 cp.async tensor-core GEMM ----------------
#define TBM 128
#define TBN 128
#define TBK 32
#define APAD 40
#define ASTAGE (TBM * APAD * 2)
#define NSTAGE 4
#define GSMEM (NSTAGE * 2 * ASTAGE)   // 81920 B -> 2 CTAs/SM

__global__ void __launch_bounds__(256, 2)
gemm_f16(const __half* __restrict__ A, int lda,
         const __half* __restrict__ B, int ldb,
         float* __restrict__ C, int ldc,
         int N, int K, const float* __restrict__ bias, int mode,
         int kchunk, size_t czstride) {
    extern __shared__ __align__(16) char smem[];
    uint32_t sA = smem_u32(smem);
    uint32_t sB = sA + NSTAGE * ASTAGE;

    int t = threadIdx.x;
    int m0 = blockIdx.y * TBM, n0 = blockIdx.x * TBN;
    int wid = t >> 5, lane = t & 31;
    int wm = (wid & 1) * 64;
    int wn = (wid >> 1) * 32;

    int kbeg = 0, kend = K;
    if (kchunk > 0) {
        kbeg = blockIdx.z * kchunk;
        kend = min(kbeg + kchunk, K);
        C += (size_t)blockIdx.z * czstride;
    }
    int Klocal = kend - kbeg;
    int nk = (Klocal + TBK - 1) / TBK;

    int a_row = wm + (lane & 15);
    int a_koff = (lane >> 4) << 3;
    int b_row = wn + ((lane >> 4) << 3) + (lane & 7);
    int b_koff = lane & 8;

    float acc[4][4][4];
    #pragma unroll
    for (int i = 0; i < 4; i++)
        #pragma unroll
        for (int j = 0; j < 4; j++)
            #pragma unroll
            for (int q = 0; q < 4; q++) acc[i][j][q] = 0.f;

    auto issue = [&](int kt) {
        if (kt < nk) {
            int buf = kt & (NSTAGE - 1);
            #pragma unroll
            for (int i = 0; i < 2; i++) {
                int idx = t + i * 256;
                int row = idx >> 2, ch = idx & 3;
                int kOff = kt * TBK + ch * 8;
                int szA = (Klocal - kOff) * 2;
                szA = szA < 0 ? 0 : (szA > 16 ? 16 : szA);
                uint32_t doff = (uint32_t)buf * ASTAGE + (uint32_t)(row * APAD + ch * 8) * 2;
                const __half* srcA = (szA > 0) ? (A + (size_t)(m0 + row) * lda + kbeg + kOff) : A;
                cpasync16(sA + doff, srcA, szA);
                int brow = n0 + row;
                int szB = (brow < N) ? szA : 0;
                const __half* srcB = (szB > 0) ? (B + (size_t)brow * ldb + kbeg + kOff) : B;
                cpasync16(sB + doff, srcB, szB);
            }
        }
        asm volatile("cp.async.commit_group;" ::: "memory");
    };

    issue(0);
    issue(1);
    issue(2);

    for (int kt = 0; kt < nk; kt++) {
        int buf = kt & (NSTAGE - 1);
        asm volatile("cp.async.wait_group 2;" ::: "memory");
        __syncthreads();
        uint32_t aBase = sA + buf * ASTAGE;
        uint32_t bBase = sB + buf * ASTAGE;
        #pragma unroll
        for (int k16 = 0; k16 < 2; k16++) {
            uint32_t af[4][4];
            #pragma unroll
            for (int mt = 0; mt < 4; mt++) {
                uint32_t addr = aBase + ((a_row + mt * 16) * APAD + k16 * 16 + a_koff) * 2;
                ldsm_x4(af[mt][0], af[mt][1], af[mt][2], af[mt][3], addr);
            }
            uint32_t bf[4][2];
            #pragma unroll
            for (int np = 0; np < 2; np++) {
                uint32_t addr = bBase + ((b_row + np * 16) * APAD + k16 * 16 + b_koff) * 2;
                uint32_t r0, r1, r2, r3;
                ldsm_x4(r0, r1, r2, r3, addr);
                bf[np * 2 + 0][0] = r0; bf[np * 2 + 0][1] = r1;
                bf[np * 2 + 1][0] = r2; bf[np * 2 + 1][1] = r3;
            }
            #pragma unroll
            for (int mt = 0; mt < 4; mt++)
                #pragma unroll
                for (int nt = 0; nt < 4; nt++)
                    mma16816(acc[mt][nt], af[mt], bf[nt][0], bf[nt][1]);
        }
        issue(kt + 3);
    }

    int qr = lane >> 2;
    int qc = (lane & 3) * 2;
    #pragma unroll
    for (int mt = 0; mt < 4; mt++) {
        #pragma unroll
        for (int nt = 0; nt < 4; nt++) {
            int cb = n0 + wn + nt * 8;
            if (cb >= N) continue;
            int c = cb + qc;
            int r0 = m0 + wm + mt * 16 + qr;
            float* p0 = C + (size_t)r0 * ldc + c;
            float* p1 = C + (size_t)(r0 + 8) * ldc + c;
            float v0 = acc[mt][nt][0], v1 = acc[mt][nt][1];
            float v2 = acc[mt][nt][2], v3 = acc[mt][nt][3];
            if (mode == 1) {
                float b0 = bias[c], b1 = bias[c + 1];
                v0 += b0; v1 += b1; v2 += b0; v3 += b1;
                v0 = (v0 > 20.f) ? v0 : log1pf(__expf(v0));
                v1 = (v1 > 20.f) ? v1 : log1pf(__expf(v1));
                v2 = (v2 > 20.f) ? v2 : log1pf(__expf(v2));
                v3 = (v3 > 20.f) ? v3 : log1pf(__expf(v3));
            }
            p0[0] = v0; p0[1] = v1;
            p1[0] = v2; p1[1] = v3;
        }
    }
}

// ---------------- fused kernels ----------------
__global__ void convert_all(const float* __restrict__ s1, int n1,
                            const float* __restrict__ s2, int n2,
                            const float* __restrict__ s3, int n3,
                            const float* __restrict__ s4, int n4,
                            const float* __restrict__ s5, int n5,
                            __half* __restrict__ d1, __half* __restrict__ d2,
                            __half* __restrict__ d3, __half* __restrict__ d4,
                            __half* __restrict__ d5) {
    int i = (blockIdx.x * blockDim.x + threadIdx.x) * 2;
    const float* s; __half* d;
    if (i < n1) { s = s1; d = d1; }
    else if ((i -= n1) < n2) { s = s2; d = d2; }
    else if ((i -= n2) < n3) { s = s3; d = d3; }
    else if ((i -= n3) < n4) { s = s4; d = d4; }
    else if ((i -= n4) < n5) { s = s5; d = d5; }
    else return;
    float2 v = *(const float2*)(s + i);
    *(__half2*)(d + i) = __floats2half2_rn(v.x, v.y);
}

__global__ void reduce_k(const float* __restrict__ part, float* __restrict__ out,
                         int n, int nz, size_t stride) {
    int i = blockIdx.x * blockDim.x + threadIdx.x;
    if (i >= n) return;
    float s = 0.f;
    for (int z = 0; z < nz; z++) s += part[(size_t)z * stride + i];
    out[i] = s;
}
__global__ void reduce_k_h(const float* __restrict__ part, float* __restrict__ out,
                           __half* __restrict__ outh, int n, int nz, size_t stride) {
    int i = blockIdx.x * blockDim.x + threadIdx.x;
    if (i >= n) return;
    float s = 0.f;
    for (int z = 0; z < nz; z++) s += part[(size_t)z * stride + i];
    out[i] = s;
    outh[i] = __float2half(s);
}

// fused: residual += split-K partials (or initial copy from src when nz==0),
// then rmsnorm -> fp16 normed row. Always (re)writes gx.
__global__ void __launch_bounds__(256)
resnorm16(const float* __restrict__ part, int nz, size_t stride,
          const float* __restrict__ src,
          float* __restrict__ gx, const float* __restrict__ w,
          __half* __restrict__ out) {
    int l = blockIdx.x;
    int tid = threadIdx.x;
    __shared__ float red[8];
    __shared__ float s_r;
    float vals[3];
    float ss = 0.f;
    #pragma unroll
    for (int i = 0; i < 3; i++) {
        int c = tid + i * 256;
        size_t o = (size_t)l * DM + c;
        float s;
        if (nz == 0) {
            s = src[o];
        } else {
            s = gx[o];
            for (int z = 0; z < nz; z++) s += part[(size_t)z * stride + o];
        }
        vals[i] = s;
        ss += s * s;
    }
    #pragma unroll
    for (int o = 16; o; o >>= 1) ss += __shfl_xor_sync(0xffffffffu, ss, o);
    if ((tid & 31) == 0) red[tid >> 5] = ss;
    __syncthreads();
    if (tid == 0) {
        float tt = 0.f;
        #pragma unroll
        for (int i = 0; i < 8; i++) tt += red[i];
        s_r = rsqrtf(tt / DM + 1e-5f);
    }
    __syncthreads();
    float r = s_r;
    #pragma unroll
    for (int i = 0; i < 3; i++) {
        int c = tid + i * 256;
        size_t o = (size_t)l * DM + c;
        gx[o] = vals[i];
        out[o] = __float2half(vals[i] * r * w[c]);
    }
}

// fused + tiled: in_proj partial-sum + causal conv + silu + res extraction
// CT_C=128 x CT_L=32 -> smem 17.9KB, 768 blocks, full occupancy
#define CT_L 32
#define CT_C 128
__global__ void __launch_bounds__(256)
fuse_conv(const float* __restrict__ p, const float* __restrict__ w,
          const float* __restrict__ b, float* __restrict__ gxc,
          __half* __restrict__ xch, float* __restrict__ gres) {
    __shared__ float xs[CT_L + 3][CT_C];
    int tid = threadIdx.x;
    int cblk = blockIdx.x % (DI / CT_C);
    int lblk = blockIdx.x / (DI / CT_C);
    int c0 = cblk * CT_C;
    int l0 = lblk * CT_L;
    const size_t S = (size_t)LSEQ * 2 * DI;
    // stage rows l0-3 .. l0+CT_L-1 of summed conv-input partials
    for (int q = tid; q < (CT_L + 3) * CT_C; q += 256) {
        int r = q >> 7, cc = q & (CT_C - 1);
        int l = l0 - 3 + r;
        float v = 0.f;
        if (l >= 0) {
            size_t o = (size_t)l * 2 * DI + c0 + cc;
            v = p[o] + p[S + o];
        }
        xs[r][cc] = v;
    }
    __syncthreads();
    int cc = tid & (CT_C - 1);
    int lh = tid >> 7;           // 0..1: which 16-row half
    int c = c0 + cc;
    float w0 = w[c * 4], w1 = w[c * 4 + 1], w2 = w[c * 4 + 2], w3 = w[c * 4 + 3];
    float bc = b[c];
    #pragma unroll 4
    for (int i = 0; i < CT_L / 2; i++) {
        int li = lh * (CT_L / 2) + i;
        int l = l0 + li;
        float acc = bc;
        acc += w0 * xs[li][cc];
        acc += w1 * xs[li + 1][cc];
        acc += w2 * xs[li + 2][cc];
        acc += w3 * xs[li + 3][cc];
        float v = acc / (1.f + __expf(-acc));
        size_t o = (size_t)l * DI + c;
        gxc[o] = v;
        xch[o] = __float2half(v);
        size_t ro = (size_t)l * 2 * DI + DI + c;
        gres[o] = p[ro] + p[S + ro];
    }
}

// ---------------- parallel scan (p1 + self-prefix p3) ----------------
__global__ void __launch_bounds__(256)
scan_p1(const float* __restrict__ delta, const float* __restrict__ u,
        const float* __restrict__ proj, const float* __restrict__ A_log,
        float* __restrict__ carryA, float* __restrict__ carryB) {
    __shared__ float sdel[CLEN][20];
    __shared__ float su[CLEN][20];
    __shared__ float sBC[CLEN][36];
    int tid = threadIdx.x;
    int gid0 = blockIdx.x * 256;
    int c = gid0 / DN;
    int r0 = gid0 - c * DN;
    int d0 = r0 >> 4;
    int l0 = c * CLEN;
    {
        int l = tid >> 2, seg = (tid & 3) * 4;
        *(float4*)&sdel[l][seg] = *(const float4*)(delta + (size_t)(l0 + l) * DI + d0 + seg);
        *(float4*)&su[l][seg]   = *(const float4*)(u     + (size_t)(l0 + l) * DI + d0 + seg);
    }
    #pragma unroll
    for (int i = 0; i < 2; i++) {
        int q = tid + i * 256;
        int l = q >> 3, seg = (q & 7) * 4;
        *(float4*)&sBC[l][seg] = *(const float4*)(proj + (size_t)(l0 + l) * PROJW + DTR + seg);
    }
    __syncthreads();
    int j = tid >> 4, n = tid & 15;
    float A = -__expf(A_log[(d0 + j) * DS + n]);
    float ap = 1.f, s = 0.f;
    #pragma unroll 4
    for (int l = 0; l < CLEN; l++) {
        float dl = sdel[l][j];
        float ul = su[l][j];
        float Bn = sBC[l][n];
        float a = __expf(dl * A);
        ap *= a;
        s = fmaf(a, s, (dl * ul) * Bn);
    }
    carryA[gid0 + tid] = ap;
    carryB[gid0 + tid] = s;
}

__global__ void __launch_bounds__(256)
scan_p3(const float* __restrict__ delta, const float* __restrict__ u,
        const float* __restrict__ proj, const float* __restrict__ gres,
        const float* __restrict__ A_log, const float* __restrict__ Dv,
        const float* __restrict__ carryA, const float* __restrict__ carryB,
        __half* __restrict__ yh) {
    __shared__ float sdel[CLEN][20];
    __shared__ float su[CLEN][20];
    __shared__ float sBC[CLEN][36];
    __shared__ float sres[CLEN][20];
    int tid = threadIdx.x;
    int gid0 = blockIdx.x * 256;
    int c = gid0 / DN;
    int r0 = gid0 - c * DN;
    int d0 = r0 >> 4;
    int l0 = c * CLEN;
    // self-computed prefix over chunks [0, c)
    float s = 0.f;
    for (int z = 0; z < c; z++) {
        int o = z * DN + r0 + tid;
        s = fmaf(carryA[o], s, carryB[o]);
    }
    {
        int l = tid >> 2, seg = (tid & 3) * 4;
        *(float4*)&sdel[l][seg] = *(const float4*)(delta + (size_t)(l0 + l) * DI + d0 + seg);
        *(float4*)&su[l][seg]   = *(const float4*)(u     + (size_t)(l0 + l) * DI + d0 + seg);
        *(float4*)&sres[l][seg] = *(const float4*)(gres  + (size_t)(l0 + l) * DI + d0 + seg);
    }
    #pragma unroll
    for (int i = 0; i < 2; i++) {
        int q = tid + i * 256;
        int l = q >> 3, seg = (q & 7) * 4;
        *(float4*)&sBC[l][seg] = *(const float4*)(proj + (size_t)(l0 + l) * PROJW + DTR + seg);
    }
    __syncthreads();
    int j = tid >> 4, n = tid & 15;
    float A = -__expf(A_log[(d0 + j) * DS + n]);
    float Dd = Dv[d0 + j];
    for (int l = 0; l < CLEN; l++) {
        float dl = sdel[l][j];
        float ul = su[l][j];
        float Bn = sBC[l][n];
        float Cn = sBC[l][16 + n];
        float a = __expf(dl * A);
        s = fmaf(a, s, (dl * ul) * Bn);
        float v = s * Cn;
        v += __shfl_xor_sync(0xffffffffu, v, 8, 16);
        v += __shfl_xor_sync(0xffffffffu, v, 4, 16);
        v += __shfl_xor_sync(0xffffffffu, v, 2, 16);
        v += __shfl_xor_sync(0xffffffffu, v, 1, 16);
        if (n == 0) {
            float res = sres[l][j];
            float g = res / (1.f + __expf(-res));
            yh[(size_t)(l0 + l) * DI + d0 + j] = __float2half((v + ul * Dd) * g);
        }
    }
}

// ---------------- host orchestration ----------------
extern "C" void kernel_launch(void* const* d_in, const int* in_sizes, int n_in,
                              void* d_out, int out_size) {
    const float* x_in      = (const float*)d_in[0];
    const float* in_proj_w = (const float*)d_in[1];
    const float* conv_w    = (const float*)d_in[2];
    const float* conv_b    = (const float*)d_in[3];
    const float* x_proj_w  = (const float*)d_in[4];
    const float* dt_proj_w = (const float*)d_in[5];
    const float* dt_proj_b = (const float*)d_in[6];
    const float* A_log     = (const float*)d_in[7];
    const float* Dv        = (const float*)d_in[8];
    const float* out_proj_w= (const float*)d_in[9];
    const float* norm_w    = (const float*)d_in[10];
    const float* norm_f_w  = (const float*)d_in[11];
    const float* head_w    = (const float*)d_in[12];
    float* out = (float*)d_out;

    float *gx, *gipp, *gxc, *gres, *gproj, *gprojp, *gdelta, *gyp, *gheadp, *gcA, *gcB;
    __half *ipw16, *xpw16, *dtw16, *opw16, *hw16, *xn16, *xch, *projh, *yh;
    cudaGetSymbolAddress((void**)&gx,     g_x);
    cudaGetSymbolAddress((void**)&gipp,   g_ipp);
    cudaGetSymbolAddress((void**)&gxc,    g_xc);
    cudaGetSymbolAddress((void**)&gres,   g_res);
    cudaGetSymbolAddress((void**)&gproj,  g_proj);
    cudaGetSymbolAddress((void**)&gprojp, g_projp);
    cudaGetSymbolAddress((void**)&gdelta, g_delta);
    cudaGetSymbolAddress((void**)&gyp,    g_yp);
    cudaGetSymbolAddress((void**)&gheadp, g_headp);
    cudaGetSymbolAddress((void**)&gcA,    g_carryA);
    cudaGetSymbolAddress((void**)&gcB,    g_carryB);
    cudaGetSymbolAddress((void**)&ipw16,  g_ipw16);
    cudaGetSymbolAddress((void**)&xpw16,  g_xpw16);
    cudaGetSymbolAddress((void**)&dtw16,  g_dtw16);
    cudaGetSymbolAddress((void**)&opw16,  g_opw16);
    cudaGetSymbolAddress((void**)&hw16,   g_hw16);
    cudaGetSymbolAddress((void**)&xn16,   g_xn16);
    cudaGetSymbolAddress((void**)&xch,    g_xch);
    cudaGetSymbolAddress((void**)&projh,  g_projh);
    cudaGetSymbolAddress((void**)&yh,     g_yh);

    cudaFuncSetAttribute(gemm_f16, cudaFuncAttributeMaxDynamicSharedMemorySize, GSMEM);

    {
        int n1 = NLAYER * 2 * DI * DM;
        int n2 = NLAYER * PROJW * DI;
        int n3 = NLAYER * DI * DTR;
        int n4 = NLAYER * DM * DI;
        int n5 = OUTD * DM;
        int total = n1 + n2 + n3 + n4 + n5;
        convert_all<<<(total / 2 + 255) / 256, 256>>>(
            in_proj_w, n1, x_proj_w, n2, dt_proj_w, n3, out_proj_w, n4, head_w, n5,
            ipw16, xpw16, dtw16, opw16, hw16);
    }

    resnorm16<<<LSEQ, 256>>>(nullptr, 0, 0, x_in, gx, norm_w, xn16);

    for (int i = 0; i < NLAYER; i++) {
        const __half* ipw = ipw16 + (size_t)i * 2 * DI * DM;
        const float*  cw  = conv_w     + (size_t)i * DI * DCONV;
        const float*  cb  = conv_b     + (size_t)i * DI;
        const __half* xpw = xpw16 + (size_t)i * PROJW * DI;
        const __half* dtw = dtw16 + (size_t)i * DI * DTR;
        const float*  dtb = dt_proj_b  + (size_t)i * DI;
        const float*  al  = A_log      + (size_t)i * DI * DS;
        const float*  dv  = Dv         + (size_t)i * DI;
        const __half* opw = opw16 + (size_t)i * DM * DI;

        gemm_f16<<<dim3(2 * DI / TBN, LSEQ / TBM, ISPLIT), 256, GSMEM>>>(
            xn16, DM, ipw, DM, gipp, 2 * DI, 2 * DI, DM, nullptr, 0,
            DM / ISPLIT, (size_t)LSEQ * 2 * DI);
        fuse_conv<<<(DI / CT_C) * (LSEQ / CT_L), 256>>>(gipp, cw, cb, gxc, xch, gres);

        gemm_f16<<<dim3(1, LSEQ / TBM, XSPLIT), 256, GSMEM>>>(
            xch, DI, xpw, DI, gprojp, PROJW, PROJW, DI, nullptr, 0,
            DI / XSPLIT, (size_t)LSEQ * PROJW);
        reduce_k_h<<<(LSEQ * PROJW + 255) / 256, 256>>>(
            gprojp, gproj, projh, LSEQ * PROJW, XSPLIT, (size_t)LSEQ * PROJW);

        gemm_f16<<<dim3(DI / TBN, LSEQ / TBM), 256, GSMEM>>>(
            projh, PROJW, dtw, DTR, gdelta, DI, DI, DTR, dtb, 1, 0, 0);

        scan_p1<<<NCHUNK * DN / 256, 256>>>(gdelta, gxc, gproj, al, gcA, gcB);
        scan_p3<<<NCHUNK * DN / 256, 256>>>(gdelta, gxc, gproj, gres, al, dv, gcA, gcB, yh);

        gemm_f16<<<dim3(DM / TBN, LSEQ / TBM, OSPLIT), 256, GSMEM>>>(
            yh, DI, opw, DI, gyp, DM, DM, DI, nullptr, 0,
            DI / OSPLIT, (size_t)LSEQ * DM);
        const float* nextw = (i + 1 < NLAYER) ? (norm_w + (size_t)(i + 1) * DM) : norm_f_w;
        resnorm16<<<LSEQ, 256>>>(gyp, OSPLIT, (size_t)LSEQ * DM, nullptr, gx, nextw, xn16);
    }

    gemm_f16<<<dim3(OUTD / TBN, LSEQ / TBM, HSPLIT), 256, GSMEM>>>(
        xn16, DM, hw16, DM, gheadp, OUTD, OUTD, DM, nullptr, 0,
        DM / HSPLIT, (size_t)LSEQ * OUTD);
    reduce_k<<<(LSEQ * OUTD + 255) / 256, 256>>>(
        gheadp, out, LSEQ * OUTD, HSPLIT, (size_t)LSEQ * OUTD);
}

// round 16
// speedup vs baseline: 1.0444x; 1.0444x over previous
#include <cuda_runtime.h>
#include <cuda_fp16.h>
#include <math.h>
#include <stdint.h>

#define LSEQ 2048
#define DM 768
#define DI 1536
#define DS 16
#define DTR 48
#define DCONV 4
#define OUTD 128
#define PROJW (DTR + 2*DS)   // 80
#define NLAYER 2
#define ISPLIT 2
#define XSPLIT 16
#define OSPLIT 3
#define HSPLIT 12
#define NCHUNK 32
#define CLEN (LSEQ / NCHUNK)   // 64
#define DN (DI * DS)           // 24576

// ---------------- scratch ----------------
__device__ float g_x[LSEQ*DM];
__device__ float g_ipp[ISPLIT*LSEQ*2*DI];
__device__ float g_xc[LSEQ*DI];
__device__ float g_proj[LSEQ*PROJW];
__device__ float g_projp[XSPLIT*LSEQ*PROJW];
__device__ float g_delta[LSEQ*DI];
__device__ float g_yp[OSPLIT*LSEQ*DM];
__device__ float g_headp[HSPLIT*LSEQ*OUTD];
__device__ float g_carryA[NCHUNK*DN];
__device__ float g_carryB[NCHUNK*DN];
// fp16 weights + activations
__device__ __half g_ipw16[NLAYER*2*DI*DM];
__device__ __half g_xpw16[NLAYER*PROJW*DI];
__device__ __half g_dtw16[NLAYER*DI*DTR];
__device__ __half g_opw16[NLAYER*DM*DI];
__device__ __half g_hw16[OUTD*DM];
__device__ __half g_xn16[LSEQ*DM];
__device__ __half g_xch[LSEQ*DI];
__device__ __half g_projh[LSEQ*PROJW];
__device__ __half g_yh[LSEQ*DI];

__device__ __forceinline__ uint32_t smem_u32(const void* p) {
    uint32_t a;
    asm("{ .reg .u64 t; cvta.to.shared.u64 t, %1; cvt.u32.u64 %0, t; }" : "=r"(a) : "l"(p));
    return a;
}
__device__ __forceinline__ void ldsm_x4(uint32_t& r0, uint32_t& r1, uint32_t& r2, uint32_t& r3, uint32_t addr) {
    asm volatile("ldmatrix.sync.aligned.m8n8.x4.shared.b16 {%0,%1,%2,%3}, [%4];"
                 : "=r"(r0), "=r"(r1), "=r"(r2), "=r"(r3) : "r"(addr));
}
__device__ __forceinline__ void mma16816(float* c, const uint32_t* a, uint32_t b0, uint32_t b1) {
    asm volatile("mma.sync.aligned.m16n8k16.row.col.f32.f16.f16.f32 "
                 "{%0,%1,%2,%3}, {%4,%5,%6,%7}, {%8,%9}, {%0,%1,%2,%3};"
                 : "+f"(c[0]), "+f"(c[1]), "+f"(c[2]), "+f"(c[3])
                 : "r"(a[0]), "r"(a[1]), "r"(a[2]), "r"(a[3]), "r"(b0), "r"(b1));
}
__device__ __forceinline__ void cpasync16(uint32_t dst, const void* src, int sz) {
    asm volatile("cp.async.cg.shared.global [%0], [%1], 16, %2;"
                 :: "r"(dst), "l"(src), "r"(sz) : "memory");
}

// ---------------- fp16 cp.async tensor-core GEMM ----------------
#define TBM 128
#define TBN 128
#define TBK 32
#define APAD 40
#define ASTAGE (TBM * APAD * 2)
#define NSTAGE 4
#define GSMEM (NSTAGE * 2 * ASTAGE)   // 81920 B -> 2 CTAs/SM

__global__ void __launch_bounds__(256, 2)
gemm_f16(const __half* __restrict__ A, int lda,
         const __half* __restrict__ B, int ldb,
         float* __restrict__ C, int ldc,
         int N, int K, const float* __restrict__ bias, int mode,
         int kchunk, size_t czstride) {
    extern __shared__ __align__(16) char smem[];
    uint32_t sA = smem_u32(smem);
    uint32_t sB = sA + NSTAGE * ASTAGE;

    int t = threadIdx.x;
    int m0 = blockIdx.y * TBM, n0 = blockIdx.x * TBN;
    int wid = t >> 5, lane = t & 31;
    int wm = (wid & 1) * 64;
    int wn = (wid >> 1) * 32;

    int kbeg = 0, kend = K;
    if (kchunk > 0) {
        kbeg = blockIdx.z * kchunk;
        kend = min(kbeg + kchunk, K);
        C += (size_t)blockIdx.z * czstride;
    }
    int Klocal = kend - kbeg;
    int nk = (Klocal + TBK - 1) / TBK;

    int a_row = wm + (lane & 15);
    int a_koff = (lane >> 4) << 3;
    int b_row = wn + ((lane >> 4) << 3) + (lane & 7);
    int b_koff = lane & 8;

    float acc[4][4][4];
    #pragma unroll
    for (int i = 0; i < 4; i++)
        #pragma unroll
        for (int j = 0; j < 4; j++)
            #pragma unroll
            for (int q = 0; q < 4; q++) acc[i][j][q] = 0.f;

    auto issue = [&](int kt) {
        if (kt < nk) {
            int buf = kt & (NSTAGE - 1);
            #pragma unroll
            for (int i = 0; i < 2; i++) {
                int idx = t + i * 256;
                int row = idx >> 2, ch = idx & 3;
                int kOff = kt * TBK + ch * 8;
                int szA = (Klocal - kOff) * 2;
                szA = szA < 0 ? 0 : (szA > 16 ? 16 : szA);
                uint32_t doff = (uint32_t)buf * ASTAGE + (uint32_t)(row * APAD + ch * 8) * 2;
                const __half* srcA = (szA > 0) ? (A + (size_t)(m0 + row) * lda + kbeg + kOff) : A;
                cpasync16(sA + doff, srcA, szA);
                int brow = n0 + row;
                int szB = (brow < N) ? szA : 0;
                const __half* srcB = (szB > 0) ? (B + (size_t)brow * ldb + kbeg + kOff) : B;
                cpasync16(sB + doff, srcB, szB);
            }
        }
        asm volatile("cp.async.commit_group;" ::: "memory");
    };

    issue(0);
    issue(1);
    issue(2);

    for (int kt = 0; kt < nk; kt++) {
        int buf = kt & (NSTAGE - 1);
        asm volatile("cp.async.wait_group 2;" ::: "memory");
        __syncthreads();
        uint32_t aBase = sA + buf * ASTAGE;
        uint32_t bBase = sB + buf * ASTAGE;
        #pragma unroll
        for (int k16 = 0; k16 < 2; k16++) {
            uint32_t af[4][4];
            #pragma unroll
            for (int mt = 0; mt < 4; mt++) {
                uint32_t addr = aBase + ((a_row + mt * 16) * APAD + k16 * 16 + a_koff) * 2;
                ldsm_x4(af[mt][0], af[mt][1], af[mt][2], af[mt][3], addr);
            }
            uint32_t bf[4][2];
            #pragma unroll
            for (int np = 0; np < 2; np++) {
                uint32_t addr = bBase + ((b_row + np * 16) * APAD + k16 * 16 + b_koff) * 2;
                uint32_t r0, r1, r2, r3;
                ldsm_x4(r0, r1, r2, r3, addr);
                bf[np * 2 + 0][0] = r0; bf[np * 2 + 0][1] = r1;
                bf[np * 2 + 1][0] = r2; bf[np * 2 + 1][1] = r3;
            }
            #pragma unroll
            for (int mt = 0; mt < 4; mt++)
                #pragma unroll
                for (int nt = 0; nt < 4; nt++)
                    mma16816(acc[mt][nt], af[mt], bf[nt][0], bf[nt][1]);
        }
        issue(kt + 3);
    }

    int qr = lane >> 2;
    int qc = (lane & 3) * 2;
    #pragma unroll
    for (int mt = 0; mt < 4; mt++) {
        #pragma unroll
        for (int nt = 0; nt < 4; nt++) {
            int cb = n0 + wn + nt * 8;
            if (cb >= N) continue;
            int c = cb + qc;
            int r0 = m0 + wm + mt * 16 + qr;
            float* p0 = C + (size_t)r0 * ldc + c;
            float* p1 = C + (size_t)(r0 + 8) * ldc + c;
            float v0 = acc[mt][nt][0], v1 = acc[mt][nt][1];
            float v2 = acc[mt][nt][2], v3 = acc[mt][nt][3];
            if (mode == 1) {
                float b0 = bias[c], b1 = bias[c + 1];
                v0 += b0; v1 += b1; v2 += b0; v3 += b1;
                v0 = (v0 > 20.f) ? v0 : log1pf(__expf(v0));
                v1 = (v1 > 20.f) ? v1 : log1pf(__expf(v1));
                v2 = (v2 > 20.f) ? v2 : log1pf(__expf(v2));
                v3 = (v3 > 20.f) ? v3 : log1pf(__expf(v3));
            }
            p0[0] = v0; p0[1] = v1;
            p1[0] = v2; p1[1] = v3;
        }
    }
}

// ---------------- fused kernels ----------------
__global__ void convert_all(const float* __restrict__ s1, int n1,
                            const float* __restrict__ s2, int n2,
                            const float* __restrict__ s3, int n3,
                            const float* __restrict__ s4, int n4,
                            const float* __restrict__ s5, int n5,
                            __half* __restrict__ d1, __half* __restrict__ d2,
                            __half* __restrict__ d3, __half* __restrict__ d4,
                            __half* __restrict__ d5) {
    int i = (blockIdx.x * blockDim.x + threadIdx.x) * 2;
    const float* s; __half* d;
    if (i < n1) { s = s1; d = d1; }
    else if ((i -= n1) < n2) { s = s2; d = d2; }
    else if ((i -= n2) < n3) { s = s3; d = d3; }
    else if ((i -= n3) < n4) { s = s4; d = d4; }
    else if ((i -= n4) < n5) { s = s5; d = d5; }
    else return;
    float2 v = *(const float2*)(s + i);
    *(__half2*)(d + i) = __floats2half2_rn(v.x, v.y);
}

__global__ void reduce_k(const float* __restrict__ part, float* __restrict__ out,
                         int n, int nz, size_t stride) {
    int i = blockIdx.x * blockDim.x + threadIdx.x;
    if (i >= n) return;
    float s = 0.f;
    for (int z = 0; z < nz; z++) s += part[(size_t)z * stride + i];
    out[i] = s;
}
__global__ void reduce_k_h(const float* __restrict__ part, float* __restrict__ out,
                           __half* __restrict__ outh, int n, int nz, size_t stride) {
    int i = blockIdx.x * blockDim.x + threadIdx.x;
    if (i >= n) return;
    float s = 0.f;
    for (int z = 0; z < nz; z++) s += part[(size_t)z * stride + i];
    out[i] = s;
    outh[i] = __float2half(s);
}

// fused: residual += split-K partials (or initial copy from src when nz==0),
// then rmsnorm -> fp16 normed row. Always (re)writes gx.
__global__ void __launch_bounds__(256)
resnorm16(const float* __restrict__ part, int nz, size_t stride,
          const float* __restrict__ src,
          float* __restrict__ gx, const float* __restrict__ w,
          __half* __restrict__ out) {
    int l = blockIdx.x;
    int tid = threadIdx.x;
    __shared__ float red[8];
    __shared__ float s_r;
    float vals[3];
    float ss = 0.f;
    #pragma unroll
    for (int i = 0; i < 3; i++) {
        int c = tid + i * 256;
        size_t o = (size_t)l * DM + c;
        float s;
        if (nz == 0) {
            s = src[o];
        } else {
            s = gx[o];
            for (int z = 0; z < nz; z++) s += part[(size_t)z * stride + o];
        }
        vals[i] = s;
        ss += s * s;
    }
    #pragma unroll
    for (int o = 16; o; o >>= 1) ss += __shfl_xor_sync(0xffffffffu, ss, o);
    if ((tid & 31) == 0) red[tid >> 5] = ss;
    __syncthreads();
    if (tid == 0) {
        float tt = 0.f;
        #pragma unroll
        for (int i = 0; i < 8; i++) tt += red[i];
        s_r = rsqrtf(tt / DM + 1e-5f);
    }
    __syncthreads();
    float r = s_r;
    #pragma unroll
    for (int i = 0; i < 3; i++) {
        int c = tid + i * 256;
        size_t o = (size_t)l * DM + c;
        gx[o] = vals[i];
        out[o] = __float2half(vals[i] * r * w[c]);
    }
}

// fused + tiled: in_proj partial-sum + causal conv + silu
// CT_C=128 x CT_L=16 -> smem 9.7KB, 1536 blocks (1.3 waves @ 8 CTAs/SM)
#define CT_L 16
#define CT_C 128
__global__ void __launch_bounds__(256)
fuse_conv(const float* __restrict__ p, const float* __restrict__ w,
          const float* __restrict__ b, float* __restrict__ gxc,
          __half* __restrict__ xch) {
    __shared__ float xs[CT_L + 3][CT_C];
    int tid = threadIdx.x;
    int cblk = blockIdx.x % (DI / CT_C);
    int lblk = blockIdx.x / (DI / CT_C);
    int c0 = cblk * CT_C;
    int l0 = lblk * CT_L;
    const size_t S = (size_t)LSEQ * 2 * DI;
    for (int q = tid; q < (CT_L + 3) * CT_C; q += 256) {
        int r = q >> 7, cc = q & (CT_C - 1);
        int l = l0 - 3 + r;
        float v = 0.f;
        if (l >= 0) {
            size_t o = (size_t)l * 2 * DI + c0 + cc;
            v = p[o] + p[S + o];
        }
        xs[r][cc] = v;
    }
    __syncthreads();
    int cc = tid & (CT_C - 1);
    int lh = tid >> 7;           // 0..1
    int c = c0 + cc;
    float w0 = w[c * 4], w1 = w[c * 4 + 1], w2 = w[c * 4 + 2], w3 = w[c * 4 + 3];
    float bc = b[c];
    #pragma unroll
    for (int i = 0; i < CT_L / 2; i++) {
        int li = lh * (CT_L / 2) + i;
        int l = l0 + li;
        float acc = bc;
        acc += w0 * xs[li][cc];
        acc += w1 * xs[li + 1][cc];
        acc += w2 * xs[li + 2][cc];
        acc += w3 * xs[li + 3][cc];
        float v = acc / (1.f + __expf(-acc));
        size_t o = (size_t)l * DI + c;
        gxc[o] = v;
        xch[o] = __float2half(v);
    }
}

// ---------------- parallel scan (p1 + self-prefix p3) ----------------
__global__ void __launch_bounds__(256)
scan_p1(const float* __restrict__ delta, const float* __restrict__ u,
        const float* __restrict__ proj, const float* __restrict__ A_log,
        float* __restrict__ carryA, float* __restrict__ carryB) {
    __shared__ float sdel[CLEN][20];
    __shared__ float su[CLEN][20];
    __shared__ float sBC[CLEN][36];
    int tid = threadIdx.x;
    int gid0 = blockIdx.x * 256;
    int c = gid0 / DN;
    int r0 = gid0 - c * DN;
    int d0 = r0 >> 4;
    int l0 = c * CLEN;
    {
        int l = tid >> 2, seg = (tid & 3) * 4;
        *(float4*)&sdel[l][seg] = *(const float4*)(delta + (size_t)(l0 + l) * DI + d0 + seg);
        *(float4*)&su[l][seg]   = *(const float4*)(u     + (size_t)(l0 + l) * DI + d0 + seg);
    }
    #pragma unroll
    for (int i = 0; i < 2; i++) {
        int q = tid + i * 256;
        int l = q >> 3, seg = (q & 7) * 4;
        *(float4*)&sBC[l][seg] = *(const float4*)(proj + (size_t)(l0 + l) * PROJW + DTR + seg);
    }
    __syncthreads();
    int j = tid >> 4, n = tid & 15;
    float A = -__expf(A_log[(d0 + j) * DS + n]);
    float ap = 1.f, s = 0.f;
    #pragma unroll 4
    for (int l = 0; l < CLEN; l++) {
        float dl = sdel[l][j];
        float ul = su[l][j];
        float Bn = sBC[l][n];
        float a = __expf(dl * A);
        ap *= a;
        s = fmaf(a, s, (dl * ul) * Bn);
    }
    carryA[gid0 + tid] = ap;
    carryB[gid0 + tid] = s;
}

__global__ void __launch_bounds__(256)
scan_p3(const float* __restrict__ delta, const float* __restrict__ u,
        const float* __restrict__ proj, const float* __restrict__ ipp,
        const float* __restrict__ A_log, const float* __restrict__ Dv,
        const float* __restrict__ carryA, const float* __restrict__ carryB,
        __half* __restrict__ yh) {
    __shared__ float sdel[CLEN][20];
    __shared__ float su[CLEN][20];
    __shared__ float sBC[CLEN][36];
    __shared__ float sres[CLEN][20];
    int tid = threadIdx.x;
    int gid0 = blockIdx.x * 256;
    int c = gid0 / DN;
    int r0 = gid0 - c * DN;
    int d0 = r0 >> 4;
    int l0 = c * CLEN;
    // self-computed prefix over chunks [0, c)
    float s = 0.f;
    for (int z = 0; z < c; z++) {
        int o = z * DN + r0 + tid;
        s = fmaf(carryA[o], s, carryB[o]);
    }
    const size_t S = (size_t)LSEQ * 2 * DI;
    {
        int l = tid >> 2, seg = (tid & 3) * 4;
        *(float4*)&sdel[l][seg] = *(const float4*)(delta + (size_t)(l0 + l) * DI + d0 + seg);
        *(float4*)&su[l][seg]   = *(const float4*)(u     + (size_t)(l0 + l) * DI + d0 + seg);
        // res = sum of in_proj split-K partials (second half of the 2*DI row)
        size_t ro = (size_t)(l0 + l) * 2 * DI + DI + d0 + seg;
        float4 r1 = *(const float4*)(ipp + ro);
        float4 r2 = *(const float4*)(ipp + S + ro);
        sres[l][seg + 0] = r1.x + r2.x;
        sres[l][seg + 1] = r1.y + r2.y;
        sres[l][seg + 2] = r1.z + r2.z;
        sres[l][seg + 3] = r1.w + r2.w;
    }
    #pragma unroll
    for (int i = 0; i < 2; i++) {
        int q = tid + i * 256;
        int l = q >> 3, seg = (q & 7) * 4;
        *(float4*)&sBC[l][seg] = *(const float4*)(proj + (size_t)(l0 + l) * PROJW + DTR + seg);
    }
    __syncthreads();
    int j = tid >> 4, n = tid & 15;
    float A = -__expf(A_log[(d0 + j) * DS + n]);
    float Dd = Dv[d0 + j];
    for (int l = 0; l < CLEN; l++) {
        float dl = sdel[l][j];
        float ul = su[l][j];
        float Bn = sBC[l][n];
        float Cn = sBC[l][16 + n];
        float a = __expf(dl * A);
        s = fmaf(a, s, (dl * ul) * Bn);
        float v = s * Cn;
        v += __shfl_xor_sync(0xffffffffu, v, 8, 16);
        v += __shfl_xor_sync(0xffffffffu, v, 4, 16);
        v += __shfl_xor_sync(0xffffffffu, v, 2, 16);
        v += __shfl_xor_sync(0xffffffffu, v, 1, 16);
        if (n == 0) {
            float res = sres[l][j];
            float g = res / (1.f + __expf(-res));
            yh[(size_t)(l0 + l) * DI + d0 + j] = __float2half((v + ul * Dd) * g);
        }
    }
}

// ---------------- host orchestration ----------------
extern "C" void kernel_launch(void* const* d_in, const int* in_sizes, int n_in,
                              void* d_out, int out_size) {
    const float* x_in      = (const float*)d_in[0];
    const float* in_proj_w = (const float*)d_in[1];
    const float* conv_w    = (const float*)d_in[2];
    const float* conv_b    = (const float*)d_in[3];
    const float* x_proj_w  = (const float*)d_in[4];
    const float* dt_proj_w = (const float*)d_in[5];
    const float* dt_proj_b = (const float*)d_in[6];
    const float* A_log     = (const float*)d_in[7];
    const float* Dv        = (const float*)d_in[8];
    const float* out_proj_w= (const float*)d_in[9];
    const float* norm_w    = (const float*)d_in[10];
    const float* norm_f_w  = (const float*)d_in[11];
    const float* head_w    = (const float*)d_in[12];
    float* out = (float*)d_out;

    float *gx, *gipp, *gxc, *gproj, *gprojp, *gdelta, *gyp, *gheadp, *gcA, *gcB;
    __half *ipw16, *xpw16, *dtw16, *opw16, *hw16, *xn16, *xch, *projh, *yh;
    cudaGetSymbolAddress((void**)&gx,     g_x);
    cudaGetSymbolAddress((void**)&gipp,   g_ipp);
    cudaGetSymbolAddress((void**)&gxc,    g_xc);
    cudaGetSymbolAddress((void**)&gproj,  g_proj);
    cudaGetSymbolAddress((void**)&gprojp, g_projp);
    cudaGetSymbolAddress((void**)&gdelta, g_delta);
    cudaGetSymbolAddress((void**)&gyp,    g_yp);
    cudaGetSymbolAddress((void**)&gheadp, g_headp);
    cudaGetSymbolAddress((void**)&gcA,    g_carryA);
    cudaGetSymbolAddress((void**)&gcB,    g_carryB);
    cudaGetSymbolAddress((void**)&ipw16,  g_ipw16);
    cudaGetSymbolAddress((void**)&xpw16,  g_xpw16);
    cudaGetSymbolAddress((void**)&dtw16,  g_dtw16);
    cudaGetSymbolAddress((void**)&opw16,  g_opw16);
    cudaGetSymbolAddress((void**)&hw16,   g_hw16);
    cudaGetSymbolAddress((void**)&xn16,   g_xn16);
    cudaGetSymbolAddress((void**)&xch,    g_xch);
    cudaGetSymbolAddress((void**)&projh,  g_projh);
    cudaGetSymbolAddress((void**)&yh,     g_yh);

    cudaFuncSetAttribute(gemm_f16, cudaFuncAttributeMaxDynamicSharedMemorySize, GSMEM);

    {
        int n1 = NLAYER * 2 * DI * DM;
        int n2 = NLAYER * PROJW * DI;
        int n3 = NLAYER * DI * DTR;
        int n4 = NLAYER * DM * DI;
        int n5 = OUTD * DM;
        int total = n1 + n2 + n3 + n4 + n5;
        convert_all<<<(total / 2 + 255) / 256, 256>>>(
            in_proj_w, n1, x_proj_w, n2, dt_proj_w, n3, out_proj_w, n4, head_w, n5,
            ipw16, xpw16, dtw16, opw16, hw16);
    }

    resnorm16<<<LSEQ, 256>>>(nullptr, 0, 0, x_in, gx, norm_w, xn16);

    for (int i = 0; i < NLAYER; i++) {
        const __half* ipw = ipw16 + (size_t)i * 2 * DI * DM;
        const float*  cw  = conv_w     + (size_t)i * DI * DCONV;
        const float*  cb  = conv_b     + (size_t)i * DI;
        const __half* xpw = xpw16 + (size_t)i * PROJW * DI;
        const __half* dtw = dtw16 + (size_t)i * DI * DTR;
        const float*  dtb = dt_proj_b  + (size_t)i * DI;
        const float*  al  = A_log      + (size_t)i * DI * DS;
        const float*  dv  = Dv         + (size_t)i * DI;
        const __half* opw = opw16 + (size_t)i * DM * DI;

        gemm_f16<<<dim3(2 * DI / TBN, LSEQ / TBM, ISPLIT), 256, GSMEM>>>(
            xn16, DM, ipw, DM, gipp, 2 * DI, 2 * DI, DM, nullptr, 0,
            DM / ISPLIT, (size_t)LSEQ * 2 * DI);
        fuse_conv<<<(DI / CT_C) * (LSEQ / CT_L), 256>>>(gipp, cw, cb, gxc, xch);

        gemm_f16<<<dim3(1, LSEQ / TBM, XSPLIT), 256, GSMEM>>>(
            xch, DI, xpw, DI, gprojp, PROJW, PROJW, DI, nullptr, 0,
            DI / XSPLIT, (size_t)LSEQ * PROJW);
        reduce_k_h<<<(LSEQ * PROJW + 255) / 256, 256>>>(
            gprojp, gproj, projh, LSEQ * PROJW, XSPLIT, (size_t)LSEQ * PROJW);

        gemm_f16<<<dim3(DI / TBN, LSEQ / TBM), 256, GSMEM>>>(
            projh, PROJW, dtw, DTR, gdelta, DI, DI, DTR, dtb, 1, 0, 0);

        scan_p1<<<NCHUNK * DN / 256, 256>>>(gdelta, gxc, gproj, al, gcA, gcB);
        scan_p3<<<NCHUNK * DN / 256, 256>>>(gdelta, gxc, gproj, gipp, al, dv, gcA, gcB, yh);

        gemm_f16<<<dim3(DM / TBN, LSEQ / TBM, OSPLIT), 256, GSMEM>>>(
            yh, DI, opw, DI, gyp, DM, DM, DI, nullptr, 0,
            DI / OSPLIT, (size_t)LSEQ * DM);
        const float* nextw = (i + 1 < NLAYER) ? (norm_w + (size_t)(i + 1) * DM) : norm_f_w;
        resnorm16<<<LSEQ, 256>>>(gyp, OSPLIT, (size_t)LSEQ * DM, nullptr, gx, nextw, xn16);
    }

    gemm_f16<<<dim3(OUTD / TBN, LSEQ / TBM, HSPLIT), 256, GSMEM>>>(
        xn16, DM, hw16, DM, gheadp, OUTD, OUTD, DM, nullptr, 0,
        DM / HSPLIT, (size_t)LSEQ * OUTD);
    reduce_k<<<(LSEQ * OUTD + 255) / 256, 256>>>(
        gheadp, out, LSEQ * OUTD, HSPLIT, (size_t)LSEQ * OUTD);
}

// round 17
// speedup vs baseline: 1.0690x; 1.0235x over previous
#include <cuda_runtime.h>
#include <cuda_fp16.h>
#include <math.h>
#include <stdint.h>

#define LSEQ 2048
#define DM 768
#define DI 1536
#define DS 16
#define DTR 48
#define DCONV 4
#define OUTD 128
#define PROJW (DTR + 2*DS)   // 80
#define NLAYER 2
#define ISPLIT 2
#define XSPLIT 16
#define OSPLIT 3
#define HSPLIT 12
#define NCHUNK 32
#define CLEN (LSEQ / NCHUNK)   // 64
#define DN (DI * DS)           // 24576
#define NBLK_PER_CHUNK (DN / 256)   // 96

// ---------------- scratch ----------------
__device__ float g_x[LSEQ*DM];
__device__ float g_ipp[ISPLIT*LSEQ*2*DI];
__device__ float g_proj[LSEQ*PROJW];
__device__ float g_projp[XSPLIT*LSEQ*PROJW];
__device__ float g_delta[LSEQ*DI];
__device__ float g_yp[OSPLIT*LSEQ*DM];
__device__ float g_headp[HSPLIT*LSEQ*OUTD];
__device__ float g_pref[NCHUNK*DN];
__device__ int   g_flag[NCHUNK*NBLK_PER_CHUNK];
// fp16 weights + activations
__device__ __half g_ipw16[NLAYER*2*DI*DM];
__device__ __half g_xpw16[NLAYER*PROJW*DI];
__device__ __half g_dtw16[NLAYER*DI*DTR];
__device__ __half g_opw16[NLAYER*DM*DI];
__device__ __half g_hw16[OUTD*DM];
__device__ __half g_xn16[LSEQ*DM];
__device__ __half g_xch[LSEQ*DI];
__device__ __half g_projh[LSEQ*PROJW];
__device__ __half g_yh[LSEQ*DI];

__device__ __forceinline__ uint32_t smem_u32(const void* p) {
    uint32_t a;
    asm("{ .reg .u64 t; cvta.to.shared.u64 t, %1; cvt.u32.u64 %0, t; }" : "=r"(a) : "l"(p));
    return a;
}
__device__ __forceinline__ void ldsm_x4(uint32_t& r0, uint32_t& r1, uint32_t& r2, uint32_t& r3, uint32_t addr) {
    asm volatile("ldmatrix.sync.aligned.m8n8.x4.shared.b16 {%0,%1,%2,%3}, [%4];"
                 : "=r"(r0), "=r"(r1), "=r"(r2), "=r"(r3) : "r"(addr));
}
__device__ __forceinline__ void mma16816(float* c, const uint32_t* a, uint32_t b0, uint32_t b1) {
    asm volatile("mma.sync.aligned.m16n8k16.row.col.f32.f16.f16.f32 "
                 "{%0,%1,%2,%3}, {%4,%5,%6,%7}, {%8,%9}, {%0,%1,%2,%3};"
                 : "+f"(c[0]), "+f"(c[1]), "+f"(c[2]), "+f"(c[3])
                 : "r"(a[0]), "r"(a[1]), "r"(a[2]), "r"(a[3]), "r"(b0), "r"(b1));
}
__device__ __forceinline__ void cpasync16(uint32_t dst, const void* src, int sz) {
    asm volatile("cp.async.cg.shared.global [%0], [%1], 16, %2;"
                 :: "r"(dst), "l"(src), "r"(sz) : "memory");
}

// ---------------- fp16 cp.async tensor-core GEMM (unchanged) ----------------
#define TBM 128
#define TBN 128
#define TBK 32
#define APAD 40
#define ASTAGE (TBM * APAD * 2)
#define NSTAGE 4
#define GSMEM (NSTAGE * 2 * ASTAGE)   // 81920 B -> 2 CTAs/SM

__global__ void __launch_bounds__(256, 2)
gemm_f16(const __half* __restrict__ A, int lda,
         const __half* __restrict__ B, int ldb,
         float* __restrict__ C, int ldc,
         int N, int K, const float* __restrict__ bias, int mode,
         int kchunk, size_t czstride) {
    extern __shared__ __align__(16) char smem[];
    uint32_t sA = smem_u32(smem);
    uint32_t sB = sA + NSTAGE * ASTAGE;

    int t = threadIdx.x;
    int m0 = blockIdx.y * TBM, n0 = blockIdx.x * TBN;
    int wid = t >> 5, lane = t & 31;
    int wm = (wid & 1) * 64;
    int wn = (wid >> 1) * 32;

    int kbeg = 0, kend = K;
    if (kchunk > 0) {
        kbeg = blockIdx.z * kchunk;
        kend = min(kbeg + kchunk, K);
        C += (size_t)blockIdx.z * czstride;
    }
    int Klocal = kend - kbeg;
    int nk = (Klocal + TBK - 1) / TBK;

    int a_row = wm + (lane & 15);
    int a_koff = (lane >> 4) << 3;
    int b_row = wn + ((lane >> 4) << 3) + (lane & 7);
    int b_koff = lane & 8;

    float acc[4][4][4];
    #pragma unroll
    for (int i = 0; i < 4; i++)
        #pragma unroll
        for (int j = 0; j < 4; j++)
            #pragma unroll
            for (int q = 0; q < 4; q++) acc[i][j][q] = 0.f;

    auto issue = [&](int kt) {
        if (kt < nk) {
            int buf = kt & (NSTAGE - 1);
            #pragma unroll
            for (int i = 0; i < 2; i++) {
                int idx = t + i * 256;
                int row = idx >> 2, ch = idx & 3;
                int kOff = kt * TBK + ch * 8;
                int szA = (Klocal - kOff) * 2;
                szA = szA < 0 ? 0 : (szA > 16 ? 16 : szA);
                uint32_t doff = (uint32_t)buf * ASTAGE + (uint32_t)(row * APAD + ch * 8) * 2;
                const __half* srcA = (szA > 0) ? (A + (size_t)(m0 + row) * lda + kbeg + kOff) : A;
                cpasync16(sA + doff, srcA, szA);
                int brow = n0 + row;
                int szB = (brow < N) ? szA : 0;
                const __half* srcB = (szB > 0) ? (B + (size_t)brow * ldb + kbeg + kOff) : B;
                cpasync16(sB + doff, srcB, szB);
            }
        }
        asm volatile("cp.async.commit_group;" ::: "memory");
    };

    issue(0);
    issue(1);
    issue(2);

    for (int kt = 0; kt < nk; kt++) {
        int buf = kt & (NSTAGE - 1);
        asm volatile("cp.async.wait_group 2;" ::: "memory");
        __syncthreads();
        uint32_t aBase = sA + buf * ASTAGE;
        uint32_t bBase = sB + buf * ASTAGE;
        #pragma unroll
        for (int k16 = 0; k16 < 2; k16++) {
            uint32_t af[4][4];
            #pragma unroll
            for (int mt = 0; mt < 4; mt++) {
                uint32_t addr = aBase + ((a_row + mt * 16) * APAD + k16 * 16 + a_koff) * 2;
                ldsm_x4(af[mt][0], af[mt][1], af[mt][2], af[mt][3], addr);
            }
            uint32_t bf[4][2];
            #pragma unroll
            for (int np = 0; np < 2; np++) {
                uint32_t addr = bBase + ((b_row + np * 16) * APAD + k16 * 16 + b_koff) * 2;
                uint32_t r0, r1, r2, r3;
                ldsm_x4(r0, r1, r2, r3, addr);
                bf[np * 2 + 0][0] = r0; bf[np * 2 + 0][1] = r1;
                bf[np * 2 + 1][0] = r2; bf[np * 2 + 1][1] = r3;
            }
            #pragma unroll
            for (int mt = 0; mt < 4; mt++)
                #pragma unroll
                for (int nt = 0; nt < 4; nt++)
                    mma16816(acc[mt][nt], af[mt], bf[nt][0], bf[nt][1]);
        }
        issue(kt + 3);
    }

    int qr = lane >> 2;
    int qc = (lane & 3) * 2;
    #pragma unroll
    for (int mt = 0; mt < 4; mt++) {
        #pragma unroll
        for (int nt = 0; nt < 4; nt++) {
            int cb = n0 + wn + nt * 8;
            if (cb >= N) continue;
            int c = cb + qc;
            int r0 = m0 + wm + mt * 16 + qr;
            float* p0 = C + (size_t)r0 * ldc + c;
            float* p1 = C + (size_t)(r0 + 8) * ldc + c;
            float v0 = acc[mt][nt][0], v1 = acc[mt][nt][1];
            float v2 = acc[mt][nt][2], v3 = acc[mt][nt][3];
            if (mode == 1) {
                float b0 = bias[c], b1 = bias[c + 1];
                v0 += b0; v1 += b1; v2 += b0; v3 += b1;
                v0 = (v0 > 20.f) ? v0 : log1pf(__expf(v0));
                v1 = (v1 > 20.f) ? v1 : log1pf(__expf(v1));
                v2 = (v2 > 20.f) ? v2 : log1pf(__expf(v2));
                v3 = (v3 > 20.f) ? v3 : log1pf(__expf(v3));
            }
            p0[0] = v0; p0[1] = v1;
            p1[0] = v2; p1[1] = v3;
        }
    }
}

// ---------------- fused kernels ----------------
__global__ void convert_all(const float* __restrict__ s1, int n1,
                            const float* __restrict__ s2, int n2,
                            const float* __restrict__ s3, int n3,
                            const float* __restrict__ s4, int n4,
                            const float* __restrict__ s5, int n5,
                            __half* __restrict__ d1, __half* __restrict__ d2,
                            __half* __restrict__ d3, __half* __restrict__ d4,
                            __half* __restrict__ d5) {
    int i = (blockIdx.x * blockDim.x + threadIdx.x) * 2;
    const float* s; __half* d;
    if (i < n1) { s = s1; d = d1; }
    else if ((i -= n1) < n2) { s = s2; d = d2; }
    else if ((i -= n2) < n3) { s = s3; d = d3; }
    else if ((i -= n3) < n4) { s = s4; d = d4; }
    else if ((i -= n4) < n5) { s = s5; d = d5; }
    else return;
    float2 v = *(const float2*)(s + i);
    *(__half2*)(d + i) = __floats2half2_rn(v.x, v.y);
}

__global__ void reduce_k(const float* __restrict__ part, float* __restrict__ out,
                         int n, int nz, size_t stride) {
    int i = blockIdx.x * blockDim.x + threadIdx.x;
    if (i >= n) return;
    float s = 0.f;
    for (int z = 0; z < nz; z++) s += part[(size_t)z * stride + i];
    out[i] = s;
}
__global__ void reduce_k_h(const float* __restrict__ part, float* __restrict__ out,
                           __half* __restrict__ outh, int n, int nz, size_t stride) {
    int i = blockIdx.x * blockDim.x + threadIdx.x;
    if (i >= n) return;
    float s = 0.f;
    for (int z = 0; z < nz; z++) s += part[(size_t)z * stride + i];
    out[i] = s;
    outh[i] = __float2half(s);
}

// fused: residual += split-K partials (or initial copy), then rmsnorm -> fp16
__global__ void __launch_bounds__(256)
resnorm16(const float* __restrict__ part, int nz, size_t stride,
          const float* __restrict__ src,
          float* __restrict__ gx, const float* __restrict__ w,
          __half* __restrict__ out) {
    int l = blockIdx.x;
    int tid = threadIdx.x;
    __shared__ float red[8];
    __shared__ float s_r;
    float vals[3];
    float ss = 0.f;
    #pragma unroll
    for (int i = 0; i < 3; i++) {
        int c = tid + i * 256;
        size_t o = (size_t)l * DM + c;
        float s;
        if (nz == 0) {
            s = src[o];
        } else {
            s = gx[o];
            for (int z = 0; z < nz; z++) s += part[(size_t)z * stride + o];
        }
        vals[i] = s;
        ss += s * s;
    }
    #pragma unroll
    for (int o = 16; o; o >>= 1) ss += __shfl_xor_sync(0xffffffffu, ss, o);
    if ((tid & 31) == 0) red[tid >> 5] = ss;
    __syncthreads();
    if (tid == 0) {
        float tt = 0.f;
        #pragma unroll
        for (int i = 0; i < 8; i++) tt += red[i];
        s_r = rsqrtf(tt / DM + 1e-5f);
    }
    __syncthreads();
    float r = s_r;
    #pragma unroll
    for (int i = 0; i < 3; i++) {
        int c = tid + i * 256;
        size_t o = (size_t)l * DM + c;
        gx[o] = vals[i];
        out[o] = __float2half(vals[i] * r * w[c]);
    }
}

// fused + tiled: in_proj partial-sum + causal conv + silu -> fp16 only.
// Also clears the scan lookback flags (2 per block; grid 1536 covers 3072 flags).
#define CT_L 16
#define CT_C 128
__global__ void __launch_bounds__(256)
fuse_conv(const float* __restrict__ p, const float* __restrict__ w,
          const float* __restrict__ b, __half* __restrict__ xch,
          int* __restrict__ flag) {
    if (threadIdx.x < 2) flag[blockIdx.x * 2 + threadIdx.x] = 0;
    __shared__ float xs[CT_L + 3][CT_C];
    int tid = threadIdx.x;
    int cblk = blockIdx.x % (DI / CT_C);
    int lblk = blockIdx.x / (DI / CT_C);
    int c0 = cblk * CT_C;
    int l0 = lblk * CT_L;
    const size_t S = (size_t)LSEQ * 2 * DI;
    for (int q = tid; q < (CT_L + 3) * CT_C; q += 256) {
        int r = q >> 7, cc = q & (CT_C - 1);
        int l = l0 - 3 + r;
        float v = 0.f;
        if (l >= 0) {
            size_t o = (size_t)l * 2 * DI + c0 + cc;
            v = p[o] + p[S + o];
        }
        xs[r][cc] = v;
    }
    __syncthreads();
    int cc = tid & (CT_C - 1);
    int lh = tid >> 7;
    int c = c0 + cc;
    float w0 = w[c * 4], w1 = w[c * 4 + 1], w2 = w[c * 4 + 2], w3 = w[c * 4 + 3];
    float bc = b[c];
    #pragma unroll
    for (int i = 0; i < CT_L / 2; i++) {
        int li = lh * (CT_L / 2) + i;
        int l = l0 + li;
        float acc = bc;
        acc += w0 * xs[li][cc];
        acc += w1 * xs[li + 1][cc];
        acc += w2 * xs[li + 2][cc];
        acc += w3 * xs[li + 3][cc];
        float v = acc / (1.f + __expf(-acc));
        xch[(size_t)l * DI + c] = __float2half(v);
    }
}

// ---------------- single-pass scan with decoupled lookback ----------------
// bid = c * 96 + b  (chunk-major: chunk 0 blocks scheduled first -> no deadlock)
__global__ void __launch_bounds__(256)
scan_fused(const float* __restrict__ delta, const float* __restrict__ ipp,
           const float* __restrict__ proj,
           const float* __restrict__ cw, const float* __restrict__ cb,
           const float* __restrict__ A_log, const float* __restrict__ Dv,
           float* __restrict__ pref, int* __restrict__ flag,
           __half* __restrict__ yh) {
    __shared__ float sdel[CLEN][20];
    __shared__ float su[CLEN][20];
    __shared__ float sBC[CLEN][36];
    __shared__ float sres[CLEN][20];
    int tid = threadIdx.x;
    int bid = blockIdx.x;
    int gid0 = bid * 256;
    int c = gid0 / DN;
    int r0 = gid0 - c * DN;
    int d0 = r0 >> 4;
    int l0 = c * CLEN;
    const size_t S = (size_t)LSEQ * 2 * DI;

    // ---- stage (once): delta, res, u (recomputed conv, bit-identical), B|C ----
    {
        int l = tid >> 2, seg = (tid & 3) * 4;
        *(float4*)&sdel[l][seg] = *(const float4*)(delta + (size_t)(l0 + l) * DI + d0 + seg);
        size_t ro = (size_t)(l0 + l) * 2 * DI + DI + d0 + seg;
        float4 r1 = *(const float4*)(ipp + ro);
        float4 r2 = *(const float4*)(ipp + S + ro);
        sres[l][seg + 0] = r1.x + r2.x;
        sres[l][seg + 1] = r1.y + r2.y;
        sres[l][seg + 2] = r1.z + r2.z;
        sres[l][seg + 3] = r1.w + r2.w;
        // u: conv over rows l-3..l at channels d0+seg..+3
        float xr[4][4];   // xr[t][ch], t=0 -> l-3
        #pragma unroll
        for (int t4 = 0; t4 < 4; t4++) {
            int lr = l0 + l - 3 + t4;
            if (lr >= 0) {
                size_t o = (size_t)lr * 2 * DI + d0 + seg;
                float4 a = *(const float4*)(ipp + o);
                float4 bb = *(const float4*)(ipp + S + o);
                xr[t4][0] = a.x + bb.x; xr[t4][1] = a.y + bb.y;
                xr[t4][2] = a.z + bb.z; xr[t4][3] = a.w + bb.w;
            } else {
                xr[t4][0] = xr[t4][1] = xr[t4][2] = xr[t4][3] = 0.f;
            }
        }
        #pragma unroll
        for (int ch = 0; ch < 4; ch++) {
            int cch = d0 + seg + ch;
            float4 wv = *(const float4*)(cw + cch * 4);
            float acc = cb[cch];
            acc += wv.x * xr[0][ch];
            acc += wv.y * xr[1][ch];
            acc += wv.z * xr[2][ch];
            acc += wv.w * xr[3][ch];
            su[l][seg + ch] = acc / (1.f + __expf(-acc));
        }
    }
    #pragma unroll
    for (int i = 0; i < 2; i++) {
        int q = tid + i * 256;
        int l = q >> 3, seg = (q & 7) * 4;
        *(float4*)&sBC[l][seg] = *(const float4*)(proj + (size_t)(l0 + l) * PROJW + DTR + seg);
    }
    __syncthreads();

    int j = tid >> 4, n = tid & 15;
    float A = -__expf(A_log[(d0 + j) * DS + n]);
    float Dd = Dv[d0 + j];

    // ---- phase A: local chunk scan -> (ap, sl) ----
    float ap = 1.f, sl = 0.f;
    #pragma unroll 4
    for (int l = 0; l < CLEN; l++) {
        float dl = sdel[l][j];
        float ul = su[l][j];
        float Bn = sBC[l][n];
        float a = __expf(dl * A);
        ap *= a;
        sl = fmaf(a, sl, (dl * ul) * Bn);
    }

    // ---- lookback: wait for chunk c-1 inclusive prefix ----
    float s_in = 0.f;
    if (c > 0) {
        if (tid == 0) {
            while (atomicAdd(&flag[bid - NBLK_PER_CHUNK], 0) == 0) {}
        }
        __syncthreads();
        s_in = *((const volatile float*)pref + (size_t)(c - 1) * DN + r0 + tid);
    }
    // publish inclusive prefix ASAP (same fp op as old scan_p2/p3 chain)
    if (c + 1 < NCHUNK) {
        pref[(size_t)c * DN + r0 + tid] = fmaf(ap, s_in, sl);
        __threadfence();
        __syncthreads();
        if (tid == 0) atomicExch(&flag[bid], 1);
    }

    // ---- phase B: replay with incoming state, emit y ----
    float s = s_in;
    for (int l = 0; l < CLEN; l++) {
        float dl = sdel[l][j];
        float ul = su[l][j];
        float Bn = sBC[l][n];
        float Cn = sBC[l][16 + n];
        float a = __expf(dl * A);
        s = fmaf(a, s, (dl * ul) * Bn);
        float v = s * Cn;
        v += __shfl_xor_sync(0xffffffffu, v, 8, 16);
        v += __shfl_xor_sync(0xffffffffu, v, 4, 16);
        v += __shfl_xor_sync(0xffffffffu, v, 2, 16);
        v += __shfl_xor_sync(0xffffffffu, v, 1, 16);
        if (n == 0) {
            float res = sres[l][j];
            float g = res / (1.f + __expf(-res));
            yh[(size_t)(l0 + l) * DI + d0 + j] = __float2half((v + ul * Dd) * g);
        }
    }
}

// ---------------- host orchestration ----------------
extern "C" void kernel_launch(void* const* d_in, const int* in_sizes, int n_in,
                              void* d_out, int out_size) {
    const float* x_in      = (const float*)d_in[0];
    const float* in_proj_w = (const float*)d_in[1];
    const float* conv_w    = (const float*)d_in[2];
    const float* conv_b    = (const float*)d_in[3];
    const float* x_proj_w  = (const float*)d_in[4];
    const float* dt_proj_w = (const float*)d_in[5];
    const float* dt_proj_b = (const float*)d_in[6];
    const float* A_log     = (const float*)d_in[7];
    const float* Dv        = (const float*)d_in[8];
    const float* out_proj_w= (const float*)d_in[9];
    const float* norm_w    = (const float*)d_in[10];
    const float* norm_f_w  = (const float*)d_in[11];
    const float* head_w    = (const float*)d_in[12];
    float* out = (float*)d_out;

    float *gx, *gipp, *gproj, *gprojp, *gdelta, *gyp, *gheadp, *gpref;
    int* gflag;
    __half *ipw16, *xpw16, *dtw16, *opw16, *hw16, *xn16, *xch, *projh, *yh;
    cudaGetSymbolAddress((void**)&gx,     g_x);
    cudaGetSymbolAddress((void**)&gipp,   g_ipp);
    cudaGetSymbolAddress((void**)&gproj,  g_proj);
    cudaGetSymbolAddress((void**)&gprojp, g_projp);
    cudaGetSymbolAddress((void**)&gdelta, g_delta);
    cudaGetSymbolAddress((void**)&gyp,    g_yp);
    cudaGetSymbolAddress((void**)&gheadp, g_headp);
    cudaGetSymbolAddress((void**)&gpref,  g_pref);
    cudaGetSymbolAddress((void**)&gflag,  g_flag);
    cudaGetSymbolAddress((void**)&ipw16,  g_ipw16);
    cudaGetSymbolAddress((void**)&xpw16,  g_xpw16);
    cudaGetSymbolAddress((void**)&dtw16,  g_dtw16);
    cudaGetSymbolAddress((void**)&opw16,  g_opw16);
    cudaGetSymbolAddress((void**)&hw16,   g_hw16);
    cudaGetSymbolAddress((void**)&xn16,   g_xn16);
    cudaGetSymbolAddress((void**)&xch,    g_xch);
    cudaGetSymbolAddress((void**)&projh,  g_projh);
    cudaGetSymbolAddress((void**)&yh,     g_yh);

    cudaFuncSetAttribute(gemm_f16, cudaFuncAttributeMaxDynamicSharedMemorySize, GSMEM);

    {
        int n1 = NLAYER * 2 * DI * DM;
        int n2 = NLAYER * PROJW * DI;
        int n3 = NLAYER * DI * DTR;
        int n4 = NLAYER * DM * DI;
        int n5 = OUTD * DM;
        int total = n1 + n2 + n3 + n4 + n5;
        convert_all<<<(total / 2 + 255) / 256, 256>>>(
            in_proj_w, n1, x_proj_w, n2, dt_proj_w, n3, out_proj_w, n4, head_w, n5,
            ipw16, xpw16, dtw16, opw16, hw16);
    }

    resnorm16<<<LSEQ, 256>>>(nullptr, 0, 0, x_in, gx, norm_w, xn16);

    for (int i = 0; i < NLAYER; i++) {
        const __half* ipw = ipw16 + (size_t)i * 2 * DI * DM;
        const float*  cw  = conv_w     + (size_t)i * DI * DCONV;
        const float*  cb  = conv_b     + (size_t)i * DI;
        const __half* xpw = xpw16 + (size_t)i * PROJW * DI;
        const __half* dtw = dtw16 + (size_t)i * DI * DTR;
        const float*  dtb = dt_proj_b  + (size_t)i * DI;
        const float*  al  = A_log      + (size_t)i * DI * DS;
        const float*  dv  = Dv         + (size_t)i * DI;
        const __half* opw = opw16 + (size_t)i * DM * DI;

        gemm_f16<<<dim3(2 * DI / TBN, LSEQ / TBM, ISPLIT), 256, GSMEM>>>(
            xn16, DM, ipw, DM, gipp, 2 * DI, 2 * DI, DM, nullptr, 0,
            DM / ISPLIT, (size_t)LSEQ * 2 * DI);
        fuse_conv<<<(DI / CT_C) * (LSEQ / CT_L), 256>>>(gipp, cw, cb, xch, gflag);

        gemm_f16<<<dim3(1, LSEQ / TBM, XSPLIT), 256, GSMEM>>>(
            xch, DI, xpw, DI, gprojp, PROJW, PROJW, DI, nullptr, 0,
            DI / XSPLIT, (size_t)LSEQ * PROJW);
        reduce_k_h<<<(LSEQ * PROJW + 255) / 256, 256>>>(
            gprojp, gproj, projh, LSEQ * PROJW, XSPLIT, (size_t)LSEQ * PROJW);

        gemm_f16<<<dim3(DI / TBN, LSEQ / TBM), 256, GSMEM>>>(
            projh, PROJW, dtw, DTR, gdelta, DI, DI, DTR, dtb, 1, 0, 0);

        scan_fused<<<NCHUNK * NBLK_PER_CHUNK, 256>>>(
            gdelta, gipp, gproj, cw, cb, al, dv, gpref, gflag, yh);

        gemm_f16<<<dim3(DM / TBN, LSEQ / TBM, OSPLIT), 256, GSMEM>>>(
            yh, DI, opw, DI, gyp, DM, DM, DI, nullptr, 0,
            DI / OSPLIT, (size_t)LSEQ * DM);
        const float* nextw = (i + 1 < NLAYER) ? (norm_w + (size_t)(i + 1) * DM) : norm_f_w;
        resnorm16<<<LSEQ, 256>>>(gyp, OSPLIT, (size_t)LSEQ * DM, nullptr, gx, nextw, xn16);
    }

    gemm_f16<<<dim3(OUTD / TBN, LSEQ / TBM, HSPLIT), 256, GSMEM>>>(
        xn16, DM, hw16, DM, gheadp, OUTD, OUTD, DM, nullptr, 0,
        DM / HSPLIT, (size_t)LSEQ * OUTD);
    reduce_k<<<(LSEQ * OUTD + 255) / 256, 256>>>(
        gheadp, out, LSEQ * OUTD, HSPLIT, (size_t)LSEQ * OUTD);
}